// round 14
// baseline (speedup 1.0000x reference)
#include <cuda_runtime.h>
#include <cuda_bf16.h>
#include <cstdint>

#define N_B 32
#define S_LEN 1024
#define HEADS 4
#define HD 32
#define EMB 128
#define LOG2E 1.4426950408889634f
#define SCALE 0.08838834764831845f      // 1/sqrt(128)
#define QSCALE (SCALE * LOG2E)

// ---------------- device scratch ----------------
__device__ __nv_bfloat16 g_qhi[N_B*HEADS*S_LEN*HD];
__device__ __nv_bfloat16 g_khi[N_B*HEADS*S_LEN*HD];
__device__ __nv_bfloat16 g_vhi[N_B*HEADS*S_LEN*HD];
__device__ __nv_bfloat16 g_vlo[N_B*HEADS*S_LEN*HD];
__device__ uint32_t g_mbits[(size_t)N_B*S_LEN*(S_LEN/32)];
__device__ uint32_t g_cxhi[(size_t)N_B*S_LEN*64];    // ctx bf16x2 (even,odd cols)
__device__ uint32_t g_cxlo[(size_t)N_B*S_LEN*64];
__device__ float g_inv[N_B*HEADS*S_LEN];             // per-row 1/rowsum
__device__ __nv_bfloat16 g_wohi[EMB*EMB];
__device__ __nv_bfloat16 g_wolo[EMB*EMB];

// ---------------- helpers ----------------
__device__ __forceinline__ uint32_t smem_u32(const void* p){
    uint32_t a;
    asm("{ .reg .u64 t; cvta.to.shared.u64 t, %1; cvt.u32.u64 %0, t; }" : "=r"(a) : "l"(p));
    return a;
}
__device__ __forceinline__ float ex2f(float x){
    float y; asm("ex2.approx.f32 %0, %1;" : "=f"(y) : "f"(x)); return y;
}
__device__ __forceinline__ uint32_t packbf(float lo, float hi){
    uint32_t d; asm("cvt.rn.bf16x2.f32 %0, %1, %2;" : "=r"(d) : "f"(hi), "f"(lo)); return d;
}
__device__ __forceinline__ void ldsm_x4(uint32_t* r, uint32_t addr){
    asm volatile("ldmatrix.sync.aligned.m8n8.x4.shared.b16 {%0,%1,%2,%3}, [%4];"
        : "=r"(r[0]), "=r"(r[1]), "=r"(r[2]), "=r"(r[3]) : "r"(addr));
}
__device__ __forceinline__ void ldsm_x4t(uint32_t* r, uint32_t addr){
    asm volatile("ldmatrix.sync.aligned.m8n8.x4.trans.shared.b16 {%0,%1,%2,%3}, [%4];"
        : "=r"(r[0]), "=r"(r[1]), "=r"(r[2]), "=r"(r[3]) : "r"(addr));
}
__device__ __forceinline__ void mma16816(float* c, const uint32_t* a, const uint32_t* b){
    asm volatile("mma.sync.aligned.m16n8k16.row.col.f32.bf16.bf16.f32 "
        "{%0,%1,%2,%3}, {%4,%5,%6,%7}, {%8,%9}, {%0,%1,%2,%3};"
        : "+f"(c[0]), "+f"(c[1]), "+f"(c[2]), "+f"(c[3])
        : "r"(a[0]), "r"(a[1]), "r"(a[2]), "r"(a[3]), "r"(b[0]), "r"(b[1]));
}
__device__ __forceinline__ void cp_async16(uint32_t dst, const void* src){
    asm volatile("cp.async.cg.shared.global [%0], [%1], 16;" :: "r"(dst), "l"(src));
}
#define CP_COMMIT() asm volatile("cp.async.commit_group;" ::: "memory")

// ---------------- smem layouts (byte offsets; K/V row stride 80B) ----------------
#define RS 80
#define BUF 10240
// attn_pv
#define PV_K0   0
#define PV_VH0  20480
#define PV_VL0  40960
#define PV_Q    61440
#define PV_MB0  71680
#define PV_TOTAL 76800
// attn_w
#define W_K0    0
#define W_Q     20480
#define W_MB0   30720
#define W_TOTAL 35840

// ============================================================
// Kernel 0a: bit-pack the mask
// ============================================================
__global__ __launch_bounds__(256) void maskbits_kernel(const int* __restrict__ mask)
{
    size_t w = (size_t)blockIdx.x * 256 + threadIdx.x;
    const int4* p = (const int4*)(mask + w * 32);
    uint32_t b = 0;
    #pragma unroll
    for (int i = 0; i < 8; i++){
        int4 v = __ldg(p + i);
        b |= (v.x != 0 ? 1u : 0u) << (i*4 + 0);
        b |= (v.y != 0 ? 1u : 0u) << (i*4 + 1);
        b |= (v.z != 0 ? 1u : 0u) << (i*4 + 2);
        b |= (v.w != 0 ? 1u : 0u) << (i*4 + 3);
    }
    g_mbits[w] = b;
}

// ============================================================
// Kernel 0b: split Wo into bf16 hi/lo
// ============================================================
__global__ __launch_bounds__(256) void woprep_kernel(const float* __restrict__ Wo)
{
    int i = blockIdx.x * 256 + threadIdx.x;      // 16384
    float w = __ldg(Wo + i);
    __nv_bfloat16 hi = __float2bfloat16(w);
    g_wohi[i] = hi;
    g_wolo[i] = __float2bfloat16(w - __bfloat162float(hi));
}

// ============================================================
// Kernel 1: projections -> bf16 (Q pre-scaled); vectorized smem reads
// ============================================================
__global__ __launch_bounds__(256) void proj_kernel(
    const float* __restrict__ vin, const float* __restrict__ kin,
    const float* __restrict__ qin,
    const float* __restrict__ Wv, const float* __restrict__ Wk,
    const float* __restrict__ Wq)
{
    __shared__ float sW[3][32*36];      // pad 36: float4-aligned rows, conflict-free
    __shared__ float srow[3][16*128];
    int t = threadIdx.x;
    for (int i = t; i < 1024; i += 256){
        int d = i >> 5, e = i & 31;
        sW[0][d*36+e] = __ldg(Wv + i);
        sW[1][d*36+e] = __ldg(Wk + i);
        sW[2][d*36+e] = __ldg(Wq + i);
    }
    int row0 = blockIdx.x * 16;
    const float4* s0 = (const float4*)(vin + (size_t)row0*128);
    const float4* s1 = (const float4*)(kin + (size_t)row0*128);
    const float4* s2 = (const float4*)(qin + (size_t)row0*128);
    #pragma unroll
    for (int i = 0; i < 2; i++){
        int idx = t + i*256;
        ((float4*)srow[0])[idx] = __ldg(s0 + idx);
        ((float4*)srow[1])[idx] = __ldg(s1 + idx);
        ((float4*)srow[2])[idx] = __ldg(s2 + idx);
    }
    __syncthreads();
    int half = t >> 7;
    int tt = t & 127;
    int h = tt >> 5, d = tt & 31;
    int n = row0 >> 10;
    int sbase = (row0 & 1023) + half*8;
    const float4* wv4 = (const float4*)&sW[0][d*36];
    const float4* wk4 = (const float4*)&sW[1][d*36];
    const float4* wq4 = (const float4*)&sW[2][d*36];
    for (int i = 0; i < 8; i++){
        int ri = half*8 + i;
        float av = 0.f, ak = 0.f, aq = 0.f;
        const float4* rv = (const float4*)&srow[0][ri*128 + h*32];
        const float4* rk = (const float4*)&srow[1][ri*128 + h*32];
        const float4* rq = (const float4*)&srow[2][ri*128 + h*32];
        #pragma unroll
        for (int e4 = 0; e4 < 8; e4++){
            float4 w0 = wv4[e4], x0 = rv[e4];
            av = fmaf(w0.x, x0.x, av); av = fmaf(w0.y, x0.y, av);
            av = fmaf(w0.z, x0.z, av); av = fmaf(w0.w, x0.w, av);
            float4 w1 = wk4[e4], x1 = rk[e4];
            ak = fmaf(w1.x, x1.x, ak); ak = fmaf(w1.y, x1.y, ak);
            ak = fmaf(w1.z, x1.z, ak); ak = fmaf(w1.w, x1.w, ak);
            float4 w2 = wq4[e4], x2 = rq[e4];
            aq = fmaf(w2.x, x2.x, aq); aq = fmaf(w2.y, x2.y, aq);
            aq = fmaf(w2.z, x2.z, aq); aq = fmaf(w2.w, x2.w, aq);
        }
        __nv_bfloat16 vh = __float2bfloat16(av);
        size_t o = ((size_t)(n*HEADS + h)*S_LEN + sbase + i)*HD + d;
        g_qhi[o] = __float2bfloat16(aq * QSCALE);
        g_khi[o] = __float2bfloat16(ak);
        g_vhi[o] = vh;
        g_vlo[o] = __float2bfloat16(av - __bfloat162float(vh));
    }
}

// ============================================================
// Kernel 2a: attn sweep 0 — QK->exp->PV, rowsums -> g_inv, ctx -> g_cx
// ============================================================
__global__ __launch_bounds__(256) void attn_pv_kernel()
{
    extern __shared__ char sm[];
    uint32_t smb = smem_u32(sm);
    int t = threadIdx.x;
    int l = t & 31, w = t >> 5;
    int bid = blockIdx.x;
    int qt = bid & 7, h = (bid >> 3) & 3, n = bid >> 5;
    int nh = n*HEADS + h;
    size_t hoff = (size_t)nh * S_LEN * HD;
    int qrow0 = qt * 128;
    int wm0 = w * 16;
    int g = l >> 2, u = l & 3;

    #pragma unroll
    for (int i = 0; i < 2; i++){
        int idx = t + i*256;
        int row = idx >> 2, part = idx & 3;
        const char* qsrc = (const char*)(g_qhi + hoff + (size_t)(qrow0+row)*HD) + part*16;
        *(uint4*)(sm + PV_Q + row*RS + part*16) = *(const uint4*)qsrc;
    }
    {
        const char* ksrc = (const char*)(g_khi + hoff);
        const char* vhsrc = (const char*)(g_vhi + hoff);
        const char* vlsrc = (const char*)(g_vlo + hoff);
        #pragma unroll
        for (int i = 0; i < 2; i++){
            int idx = t + i*256;
            int row = idx >> 2, part = idx & 3;
            int go = row*64 + part*16, so = row*RS + part*16;
            cp_async16(smb + PV_K0  + so, ksrc + go);
            cp_async16(smb + PV_VH0 + so, vhsrc + go);
            cp_async16(smb + PV_VL0 + so, vlsrc + go);
        }
        if (t < 128)
            cp_async16(smb + PV_MB0 + t*16,
                       g_mbits + ((size_t)n*S_LEN + qrow0 + t)*32);
        CP_COMMIT();
    }
    __syncthreads();

    uint32_t qh0[4], qh1[4];
    {
        uint32_t rowb = (uint32_t)((wm0 + ((l & 8) ? 8 : 0) + (l & 7))*RS + ((l & 16) ? 16 : 0));
        ldsm_x4(qh0, smb + PV_Q + rowb);
        ldsm_x4(qh1, smb + PV_Q + rowb + 32);
    }

    float pv[4][4];
    #pragma unroll
    for (int i = 0; i < 4; i++){ pv[i][0]=0.f; pv[i][1]=0.f; pv[i][2]=0.f; pv[i][3]=0.f; }
    float l_r = 0.f, l_r8 = 0.f;

    for (int it = 0; it < 8; it++){
        int buf = it & 1;
        if (it < 7){
            int kt2 = it + 1, b2 = kt2 & 1;
            const char* ksrc = (const char*)(g_khi + hoff + (size_t)kt2*128*HD);
            const char* vhsrc = (const char*)(g_vhi + hoff + (size_t)kt2*128*HD);
            const char* vlsrc = (const char*)(g_vlo + hoff + (size_t)kt2*128*HD);
            #pragma unroll
            for (int i = 0; i < 2; i++){
                int idx = t + i*256;
                int row = idx >> 2, part = idx & 3;
                int go = row*64 + part*16, so = row*RS + part*16;
                cp_async16(smb + PV_K0  + b2*BUF + so, ksrc + go);
                cp_async16(smb + PV_VH0 + b2*BUF + so, vhsrc + go);
                cp_async16(smb + PV_VL0 + b2*BUF + so, vlsrc + go);
            }
            if (t < 128)
                cp_async16(smb + PV_MB0 + b2*2048 + t*16,
                           g_mbits + ((size_t)n*S_LEN + qrow0 + t)*32 + kt2*4);
            CP_COMMIT();
            asm volatile("cp.async.wait_group 1;" ::: "memory");
        } else {
            asm volatile("cp.async.wait_group 0;" ::: "memory");
        }
        __syncthreads();

        uint32_t kbase  = smb + PV_K0  + buf*BUF;
        uint32_t vhbase = smb + PV_VH0 + buf*BUF;
        uint32_t vlbase = smb + PV_VL0 + buf*BUF;
        const uint32_t* mb = (const uint32_t*)(sm + PV_MB0 + buf*2048);

        uint32_t wr[4], wr8[4];
        #pragma unroll
        for (int j = 0; j < 4; j++){ wr[j] = mb[g*4 + j]; wr8[j] = mb[(g+8)*4 + j]; }

        #pragma unroll
        for (int kc = 0; kc < 8; kc++){
            uint32_t bh0[4], bh1[4];
            uint32_t rbk = (uint32_t)((kc*16 + ((l & 16) ? 8 : 0) + (l & 7))*RS + ((l & 8) ? 16 : 0));
            ldsm_x4(bh0, kbase + rbk);
            ldsm_x4(bh1, kbase + rbk + 32);
            float qk0[4] = {0.f,0.f,0.f,0.f};
            float qk1[4] = {0.f,0.f,0.f,0.f};
            mma16816(qk0, qh0, bh0);   mma16816(qk1, qh0, bh0+2);
            mma16816(qk0, qh1, bh1);   mma16816(qk1, qh1, bh1+2);

            uint32_t w0 = wr[kc >> 1], w8 = wr8[kc >> 1];
            int sh0 = ((2*kc) & 3)*8 + u*2;
            int sh1 = ((2*kc+1) & 3)*8 + u*2;
            float e0 = ((w0 >> sh0)     & 1) ? ex2f(qk0[0]) : 0.f;
            float e1 = ((w0 >> (sh0+1)) & 1) ? ex2f(qk0[1]) : 0.f;
            float e2 = ((w8 >> sh0)     & 1) ? ex2f(qk0[2]) : 0.f;
            float e3 = ((w8 >> (sh0+1)) & 1) ? ex2f(qk0[3]) : 0.f;
            float e4 = ((w0 >> sh1)     & 1) ? ex2f(qk1[0]) : 0.f;
            float e5 = ((w0 >> (sh1+1)) & 1) ? ex2f(qk1[1]) : 0.f;
            float e6 = ((w8 >> sh1)     & 1) ? ex2f(qk1[2]) : 0.f;
            float e7 = ((w8 >> (sh1+1)) & 1) ? ex2f(qk1[3]) : 0.f;
            l_r  += e0 + e1 + e4 + e5;
            l_r8 += e2 + e3 + e6 + e7;

            uint32_t ah[4], al[4];
            ah[0] = packbf(e0, e1);
            ah[1] = packbf(e2, e3);
            ah[2] = packbf(e4, e5);
            ah[3] = packbf(e6, e7);
            al[0] = packbf(e0 - __uint_as_float(ah[0] << 16), e1 - __uint_as_float(ah[0] & 0xffff0000u));
            al[1] = packbf(e2 - __uint_as_float(ah[1] << 16), e3 - __uint_as_float(ah[1] & 0xffff0000u));
            al[2] = packbf(e4 - __uint_as_float(ah[2] << 16), e5 - __uint_as_float(ah[2] & 0xffff0000u));
            al[3] = packbf(e6 - __uint_as_float(ah[3] << 16), e7 - __uint_as_float(ah[3] & 0xffff0000u));

            uint32_t vh0[4], vh1[4], vl0[4], vl1[4];
            uint32_t rbv = (uint32_t)((kc*16 + ((l & 8) ? 8 : 0) + (l & 7))*RS + ((l & 16) ? 16 : 0));
            ldsm_x4t(vh0, vhbase + rbv);
            ldsm_x4t(vh1, vhbase + rbv + 32);
            ldsm_x4t(vl0, vlbase + rbv);
            ldsm_x4t(vl1, vlbase + rbv + 32);
            mma16816(pv[0], ah, vh0);   mma16816(pv[1], ah, vh0+2);
            mma16816(pv[2], ah, vh1);   mma16816(pv[3], ah, vh1+2);
            mma16816(pv[0], al, vh0);   mma16816(pv[1], al, vh0+2);
            mma16816(pv[2], al, vh1);   mma16816(pv[3], al, vh1+2);
            mma16816(pv[0], ah, vl0);   mma16816(pv[1], ah, vl0+2);
            mma16816(pv[2], ah, vl1);   mma16816(pv[3], ah, vl1+2);
        }
        __syncthreads();
    }

    // ---- reduce rowsums, write inv + normalized ctx (bf16 hi/lo)
    l_r  += __shfl_xor_sync(0xffffffffu, l_r, 1);
    l_r  += __shfl_xor_sync(0xffffffffu, l_r, 2);
    l_r8 += __shfl_xor_sync(0xffffffffu, l_r8, 1);
    l_r8 += __shfl_xor_sync(0xffffffffu, l_r8, 2);
    float inv_r  = 1.0f / l_r;
    float inv_r8 = 1.0f / l_r8;
    if (u == 0){
        g_inv[nh*S_LEN + qrow0 + wm0 + g]     = inv_r;
        g_inv[nh*S_LEN + qrow0 + wm0 + g + 8] = inv_r8;
    }
    size_t r0 = (size_t)(n*S_LEN + qrow0 + wm0 + g);
    size_t r8 = r0 + 8;
    #pragma unroll
    for (int nt = 0; nt < 4; nt++){
        float x0 = pv[nt][0]*inv_r,  x1 = pv[nt][1]*inv_r;
        float x2 = pv[nt][2]*inv_r8, x3 = pv[nt][3]*inv_r8;
        uint32_t h0 = packbf(x0, x1);
        uint32_t h1 = packbf(x2, x3);
        uint32_t l0 = packbf(x0 - __uint_as_float(h0 << 16),
                             x1 - __uint_as_float(h0 & 0xffff0000u));
        uint32_t l1 = packbf(x2 - __uint_as_float(h1 << 16),
                             x3 - __uint_as_float(h1 & 0xffff0000u));
        int ci = h*16 + nt*4 + u;
        g_cxhi[r0*64 + ci] = h0;
        g_cxlo[r0*64 + ci] = l0;
        g_cxhi[r8*64 + ci] = h1;
        g_cxlo[r8*64 + ci] = l1;
    }
}

// ============================================================
// Kernel 2b: attn sweep 1 — recompute QK->exp, write normalized attw.
// No V smem -> 35.8KB smem, low regs -> ~5 CTAs/SM.
// ============================================================
__global__ __launch_bounds__(256) void attn_w_kernel(float* __restrict__ attw)
{
    extern __shared__ char sm[];
    uint32_t smb = smem_u32(sm);
    int t = threadIdx.x;
    int l = t & 31, w = t >> 5;
    int bid = blockIdx.x;
    int qt = bid & 7, h = (bid >> 3) & 3, n = bid >> 5;
    int nh = n*HEADS + h;
    size_t hoff = (size_t)nh * S_LEN * HD;
    int qrow0 = qt * 128;
    int wm0 = w * 16;
    int g = l >> 2, u = l & 3;

    #pragma unroll
    for (int i = 0; i < 2; i++){
        int idx = t + i*256;
        int row = idx >> 2, part = idx & 3;
        const char* qsrc = (const char*)(g_qhi + hoff + (size_t)(qrow0+row)*HD) + part*16;
        *(uint4*)(sm + W_Q + row*RS + part*16) = *(const uint4*)qsrc;
    }
    {
        const char* ksrc = (const char*)(g_khi + hoff);
        #pragma unroll
        for (int i = 0; i < 2; i++){
            int idx = t + i*256;
            int row = idx >> 2, part = idx & 3;
            cp_async16(smb + W_K0 + row*RS + part*16, ksrc + row*64 + part*16);
        }
        if (t < 128)
            cp_async16(smb + W_MB0 + t*16,
                       g_mbits + ((size_t)n*S_LEN + qrow0 + t)*32);
        CP_COMMIT();
    }
    float inv_r  = __ldg(g_inv + nh*S_LEN + qrow0 + wm0 + g);
    float inv_r8 = __ldg(g_inv + nh*S_LEN + qrow0 + wm0 + g + 8);
    __syncthreads();

    uint32_t qh0[4], qh1[4];
    {
        uint32_t rowb = (uint32_t)((wm0 + ((l & 8) ? 8 : 0) + (l & 7))*RS + ((l & 16) ? 16 : 0));
        ldsm_x4(qh0, smb + W_Q + rowb);
        ldsm_x4(qh1, smb + W_Q + rowb + 32);
    }

    float* wbase = attw + ((size_t)nh * S_LEN + qrow0) * S_LEN;

    for (int it = 0; it < 8; it++){
        int buf = it & 1;
        if (it < 7){
            int kt2 = it + 1, b2 = kt2 & 1;
            const char* ksrc = (const char*)(g_khi + hoff + (size_t)kt2*128*HD);
            #pragma unroll
            for (int i = 0; i < 2; i++){
                int idx = t + i*256;
                int row = idx >> 2, part = idx & 3;
                cp_async16(smb + W_K0 + b2*BUF + row*RS + part*16, ksrc + row*64 + part*16);
            }
            if (t < 128)
                cp_async16(smb + W_MB0 + b2*2048 + t*16,
                           g_mbits + ((size_t)n*S_LEN + qrow0 + t)*32 + kt2*4);
            CP_COMMIT();
            asm volatile("cp.async.wait_group 1;" ::: "memory");
        } else {
            asm volatile("cp.async.wait_group 0;" ::: "memory");
        }
        __syncthreads();

        uint32_t kbase = smb + W_K0 + buf*BUF;
        const uint32_t* mb = (const uint32_t*)(sm + W_MB0 + buf*2048);
        uint32_t wr[4], wr8[4];
        #pragma unroll
        for (int j = 0; j < 4; j++){ wr[j] = mb[g*4 + j]; wr8[j] = mb[(g+8)*4 + j]; }

        #pragma unroll
        for (int np = 0; np < 8; np++){
            uint32_t bh0[4], bh1[4];
            uint32_t rbk = (uint32_t)((np*16 + ((l & 16) ? 8 : 0) + (l & 7))*RS + ((l & 8) ? 16 : 0));
            ldsm_x4(bh0, kbase + rbk);
            ldsm_x4(bh1, kbase + rbk + 32);
            float qk0[4] = {0.f,0.f,0.f,0.f};
            float qk1[4] = {0.f,0.f,0.f,0.f};
            mma16816(qk0, qh0, bh0);   mma16816(qk1, qh0, bh0+2);
            mma16816(qk0, qh1, bh1);   mma16816(qk1, qh1, bh1+2);

            uint32_t w0 = wr[np >> 1], w8 = wr8[np >> 1];
            int sh0 = ((2*np) & 3)*8 + u*2;
            int sh1 = ((2*np+1) & 3)*8 + u*2;
            float e0 = ((w0 >> sh0)     & 1) ? ex2f(qk0[0]) : 0.f;
            float e1 = ((w0 >> (sh0+1)) & 1) ? ex2f(qk0[1]) : 0.f;
            float e2 = ((w8 >> sh0)     & 1) ? ex2f(qk0[2]) : 0.f;
            float e3 = ((w8 >> (sh0+1)) & 1) ? ex2f(qk0[3]) : 0.f;
            float e4 = ((w0 >> sh1)     & 1) ? ex2f(qk1[0]) : 0.f;
            float e5 = ((w0 >> (sh1+1)) & 1) ? ex2f(qk1[1]) : 0.f;
            float e6 = ((w8 >> sh1)     & 1) ? ex2f(qk1[2]) : 0.f;
            float e7 = ((w8 >> (sh1+1)) & 1) ? ex2f(qk1[3]) : 0.f;

            float* wr0p = wbase + (size_t)(wm0 + g)*S_LEN     + it*128 + np*16 + u*2;
            float* wr8p = wbase + (size_t)(wm0 + g + 8)*S_LEN + it*128 + np*16 + u*2;
            float2 o;
            o.x = e0*inv_r;  o.y = e1*inv_r;  *(float2*)(wr0p) = o;
            o.x = e4*inv_r;  o.y = e5*inv_r;  *(float2*)(wr0p + 8) = o;
            o.x = e2*inv_r8; o.y = e3*inv_r8; *(float2*)(wr8p) = o;
            o.x = e6*inv_r8; o.y = e7*inv_r8; *(float2*)(wr8p + 8) = o;
        }
        __syncthreads();
    }
}

// ============================================================
// Kernel 3: out = ctx @ Wo.T + bo via HMMA (ctx bf16 hi/lo, Wo hi/lo)
// ============================================================
#define ORS 272
__global__ __launch_bounds__(256) void out_kernel(
    const float* __restrict__ bo, float* __restrict__ out)
{
    extern __shared__ char sm[];
    uint32_t smb = smem_u32(sm);
    char* swhi = sm;
    char* swlo = sm + 128*ORS;
    float* sbo = (float*)(sm + 2*128*ORS);
    int t = threadIdx.x;
    int l = t & 31, w = t >> 5;
    int g = l >> 2, u = l & 3;

    #pragma unroll
    for (int i = 0; i < 8; i++){
        int idx = t + i*256;
        int row = idx >> 4, part = idx & 15;
        *(uint4*)(swhi + row*ORS + part*16) = ((const uint4*)g_wohi)[idx];
        *(uint4*)(swlo + row*ORS + part*16) = ((const uint4*)g_wolo)[idx];
    }
    if (t < 128) sbo[t] = __ldg(bo + t);
    __syncthreads();

    int R0 = blockIdx.x*128 + w*16;
    float c[16][4];
    #pragma unroll
    for (int i = 0; i < 16; i++){ c[i][0]=0.f; c[i][1]=0.f; c[i][2]=0.f; c[i][3]=0.f; }

    #pragma unroll
    for (int c8 = 0; c8 < 8; c8++){
        uint32_t ah[4], al[4];
        size_t rA = (size_t)(R0 + g)*64 + c8*8 + u;
        size_t rB = (size_t)(R0 + g + 8)*64 + c8*8 + u;
        ah[0] = __ldg(g_cxhi + rA);     ah[1] = __ldg(g_cxhi + rB);
        ah[2] = __ldg(g_cxhi + rA + 4); ah[3] = __ldg(g_cxhi + rB + 4);
        al[0] = __ldg(g_cxlo + rA);     al[1] = __ldg(g_cxlo + rB);
        al[2] = __ldg(g_cxlo + rA + 4); al[3] = __ldg(g_cxlo + rB + 4);
        #pragma unroll
        for (int np = 0; np < 8; np++){
            uint32_t bh[4], bl[4];
            uint32_t rb = (uint32_t)((np*16 + ((l & 16) ? 8 : 0) + (l & 7))*ORS + ((l & 8) ? 16 : 0) + c8*32);
            ldsm_x4(bh, smb + rb);
            ldsm_x4(bl, smb + 128*ORS + rb);
            mma16816(c[2*np],   ah, bh);     mma16816(c[2*np+1], ah, bh+2);
            mma16816(c[2*np],   al, bh);     mma16816(c[2*np+1], al, bh+2);
            mma16816(c[2*np],   ah, bl);     mma16816(c[2*np+1], ah, bl+2);
        }
    }

    float* o0 = out + (size_t)(R0 + g)*EMB + u*2;
    float* o8 = out + (size_t)(R0 + g + 8)*EMB + u*2;
    #pragma unroll
    for (int nt = 0; nt < 16; nt++){
        int col = nt*8 + u*2;
        float2 a; a.x = c[nt][0] + sbo[col]; a.y = c[nt][1] + sbo[col+1];
        float2 b; b.x = c[nt][2] + sbo[col]; b.y = c[nt][3] + sbo[col+1];
        *(float2*)(o0 + nt*8) = a;
        *(float2*)(o8 + nt*8) = b;
    }
}

// ============================================================
extern "C" void kernel_launch(void* const* d_in, const int* in_sizes, int n_in,
                              void* d_out, int out_size)
{
    const float* values = (const float*)d_in[0];
    const float* keys   = (const float*)d_in[1];
    const float* query  = (const float*)d_in[2];
    const int*   mask   = (const int*)d_in[3];
    const float* Wv     = (const float*)d_in[4];
    const float* Wk     = (const float*)d_in[5];
    const float* Wq     = (const float*)d_in[6];
    const float* Wo     = (const float*)d_in[7];
    const float* bo     = (const float*)d_in[8];

    float* out  = (float*)d_out;
    float* attw = out + (size_t)N_B*S_LEN*EMB;   // tuple order: (out, attention_weights)

    cudaFuncSetAttribute(attn_pv_kernel, cudaFuncAttributeMaxDynamicSharedMemorySize, PV_TOTAL);
    cudaFuncSetAttribute(attn_w_kernel,  cudaFuncAttributeMaxDynamicSharedMemorySize, W_TOTAL);
    cudaFuncSetAttribute(out_kernel,     cudaFuncAttributeMaxDynamicSharedMemorySize, 2*128*ORS + 512);

    maskbits_kernel<<<(N_B*S_LEN*(S_LEN/32))/256, 256>>>(mask);
    woprep_kernel<<<EMB*EMB/256, 256>>>(Wo);
    proj_kernel<<<(N_B*S_LEN)/16, 256>>>(values, keys, query, Wv, Wk, Wq);
    attn_pv_kernel<<<N_B*HEADS*(S_LEN/128), 256, PV_TOTAL>>>();
    attn_w_kernel<<<N_B*HEADS*(S_LEN/128), 256, W_TOTAL>>>(attw);
    out_kernel<<<(N_B*S_LEN)/128, 256, 2*128*ORS + 512>>>(bo, out);
}

// round 15
// speedup vs baseline: 1.0440x; 1.0440x over previous
#include <cuda_runtime.h>
#include <cuda_bf16.h>
#include <cstdint>

#define N_B 32
#define S_LEN 1024
#define HEADS 4
#define HD 32
#define EMB 128
#define LOG2E 1.4426950408889634f
#define SCALE 0.08838834764831845f      // 1/sqrt(128)
#define QSCALE (SCALE * LOG2E)

// ---------------- device scratch ----------------
__device__ __nv_bfloat16 g_qhi[N_B*HEADS*S_LEN*HD];
__device__ __nv_bfloat16 g_khi[N_B*HEADS*S_LEN*HD];
__device__ __nv_bfloat16 g_vhi[N_B*HEADS*S_LEN*HD];
__device__ __nv_bfloat16 g_vlo[N_B*HEADS*S_LEN*HD];
__device__ uint32_t g_mbits[(size_t)N_B*S_LEN*(S_LEN/32)];
__device__ uint32_t g_cxhi[(size_t)N_B*S_LEN*64];    // ctx bf16x2 (even,odd cols)
__device__ uint32_t g_cxlo[(size_t)N_B*S_LEN*64];
__device__ __nv_bfloat16 g_wohi[EMB*EMB];
__device__ __nv_bfloat16 g_wolo[EMB*EMB];

// ---------------- helpers ----------------
__device__ __forceinline__ uint32_t smem_u32(const void* p){
    uint32_t a;
    asm("{ .reg .u64 t; cvta.to.shared.u64 t, %1; cvt.u32.u64 %0, t; }" : "=r"(a) : "l"(p));
    return a;
}
__device__ __forceinline__ float ex2f(float x){
    float y; asm("ex2.approx.f32 %0, %1;" : "=f"(y) : "f"(x)); return y;
}
__device__ __forceinline__ uint32_t packbf(float lo, float hi){
    uint32_t d; asm("cvt.rn.bf16x2.f32 %0, %1, %2;" : "=r"(d) : "f"(hi), "f"(lo)); return d;
}
__device__ __forceinline__ void ldsm_x4(uint32_t* r, uint32_t addr){
    asm volatile("ldmatrix.sync.aligned.m8n8.x4.shared.b16 {%0,%1,%2,%3}, [%4];"
        : "=r"(r[0]), "=r"(r[1]), "=r"(r[2]), "=r"(r[3]) : "r"(addr));
}
__device__ __forceinline__ void ldsm_x4t(uint32_t* r, uint32_t addr){
    asm volatile("ldmatrix.sync.aligned.m8n8.x4.trans.shared.b16 {%0,%1,%2,%3}, [%4];"
        : "=r"(r[0]), "=r"(r[1]), "=r"(r[2]), "=r"(r[3]) : "r"(addr));
}
__device__ __forceinline__ void mma16816(float* c, const uint32_t* a, const uint32_t* b){
    asm volatile("mma.sync.aligned.m16n8k16.row.col.f32.bf16.bf16.f32 "
        "{%0,%1,%2,%3}, {%4,%5,%6,%7}, {%8,%9}, {%0,%1,%2,%3};"
        : "+f"(c[0]), "+f"(c[1]), "+f"(c[2]), "+f"(c[3])
        : "r"(a[0]), "r"(a[1]), "r"(a[2]), "r"(a[3]), "r"(b[0]), "r"(b[1]));
}
__device__ __forceinline__ void cp_async16(uint32_t dst, const void* src){
    asm volatile("cp.async.cg.shared.global [%0], [%1], 16;" :: "r"(dst), "l"(src));
}
#define CP_COMMIT() asm volatile("cp.async.commit_group;" ::: "memory")

// ---------------- attn smem layout (byte offsets; row stride 80B) ----------------
#define RS 80
#define BUF 10240
#define SM_K0  0
#define SM_VH0 20480
#define SM_VL0 40960
#define SM_Q   61440
#define SM_MB0 71680
#define SM_TOTAL 76800

// ============================================================
// Kernel 0a: bit-pack the mask
// ============================================================
__global__ __launch_bounds__(256) void maskbits_kernel(const int* __restrict__ mask)
{
    size_t w = (size_t)blockIdx.x * 256 + threadIdx.x;
    const int4* p = (const int4*)(mask + w * 32);
    uint32_t b = 0;
    #pragma unroll
    for (int i = 0; i < 8; i++){
        int4 v = __ldg(p + i);
        b |= (v.x != 0 ? 1u : 0u) << (i*4 + 0);
        b |= (v.y != 0 ? 1u : 0u) << (i*4 + 1);
        b |= (v.z != 0 ? 1u : 0u) << (i*4 + 2);
        b |= (v.w != 0 ? 1u : 0u) << (i*4 + 3);
    }
    g_mbits[w] = b;
}

// ============================================================
// Kernel 0b: split Wo into bf16 hi/lo
// ============================================================
__global__ __launch_bounds__(256) void woprep_kernel(const float* __restrict__ Wo)
{
    int i = blockIdx.x * 256 + threadIdx.x;      // 16384
    float w = __ldg(Wo + i);
    __nv_bfloat16 hi = __float2bfloat16(w);
    g_wohi[i] = hi;
    g_wolo[i] = __float2bfloat16(w - __bfloat162float(hi));
}

// ============================================================
// Kernel 1: projections -> bf16 (Q pre-scaled); vectorized smem reads
// ============================================================
__global__ __launch_bounds__(256) void proj_kernel(
    const float* __restrict__ vin, const float* __restrict__ kin,
    const float* __restrict__ qin,
    const float* __restrict__ Wv, const float* __restrict__ Wk,
    const float* __restrict__ Wq)
{
    __shared__ float sW[3][32*36];      // pad 36: float4-aligned rows, conflict-free
    __shared__ float srow[3][16*128];
    int t = threadIdx.x;
    for (int i = t; i < 1024; i += 256){
        int d = i >> 5, e = i & 31;
        sW[0][d*36+e] = __ldg(Wv + i);
        sW[1][d*36+e] = __ldg(Wk + i);
        sW[2][d*36+e] = __ldg(Wq + i);
    }
    int row0 = blockIdx.x * 16;
    const float4* s0 = (const float4*)(vin + (size_t)row0*128);
    const float4* s1 = (const float4*)(kin + (size_t)row0*128);
    const float4* s2 = (const float4*)(qin + (size_t)row0*128);
    #pragma unroll
    for (int i = 0; i < 2; i++){
        int idx = t + i*256;
        ((float4*)srow[0])[idx] = __ldg(s0 + idx);
        ((float4*)srow[1])[idx] = __ldg(s1 + idx);
        ((float4*)srow[2])[idx] = __ldg(s2 + idx);
    }
    __syncthreads();
    int half = t >> 7;
    int tt = t & 127;
    int h = tt >> 5, d = tt & 31;
    int n = row0 >> 10;
    int sbase = (row0 & 1023) + half*8;
    const float4* wv4 = (const float4*)&sW[0][d*36];
    const float4* wk4 = (const float4*)&sW[1][d*36];
    const float4* wq4 = (const float4*)&sW[2][d*36];
    for (int i = 0; i < 8; i++){
        int ri = half*8 + i;
        float av = 0.f, ak = 0.f, aq = 0.f;
        const float4* rv = (const float4*)&srow[0][ri*128 + h*32];
        const float4* rk = (const float4*)&srow[1][ri*128 + h*32];
        const float4* rq = (const float4*)&srow[2][ri*128 + h*32];
        #pragma unroll
        for (int e4 = 0; e4 < 8; e4++){
            float4 w0 = wv4[e4], x0 = rv[e4];
            av = fmaf(w0.x, x0.x, av); av = fmaf(w0.y, x0.y, av);
            av = fmaf(w0.z, x0.z, av); av = fmaf(w0.w, x0.w, av);
            float4 w1 = wk4[e4], x1 = rk[e4];
            ak = fmaf(w1.x, x1.x, ak); ak = fmaf(w1.y, x1.y, ak);
            ak = fmaf(w1.z, x1.z, ak); ak = fmaf(w1.w, x1.w, ak);
            float4 w2 = wq4[e4], x2 = rq[e4];
            aq = fmaf(w2.x, x2.x, aq); aq = fmaf(w2.y, x2.y, aq);
            aq = fmaf(w2.z, x2.z, aq); aq = fmaf(w2.w, x2.w, aq);
        }
        __nv_bfloat16 vh = __float2bfloat16(av);
        size_t o = ((size_t)(n*HEADS + h)*S_LEN + sbase + i)*HD + d;
        g_qhi[o] = __float2bfloat16(aq * QSCALE);
        g_khi[o] = __float2bfloat16(ak);
        g_vhi[o] = vh;
        g_vlo[o] = __float2bfloat16(av - __bfloat162float(vh));
    }
}

// ============================================================
// Kernel 2: fused HMMA attention (R13 structure), cp.async double-buffered,
// per-chunk QK->exp->PV fusion; mask words hoisted per tile.
// ============================================================
__global__ __launch_bounds__(256) void attn_kernel(float* __restrict__ attw)
{
    extern __shared__ char sm[];
    uint32_t smb = smem_u32(sm);
    int t = threadIdx.x;
    int l = t & 31, w = t >> 5;
    int bid = blockIdx.x;
    int qt = bid & 7, h = (bid >> 3) & 3, n = bid >> 5;   // qt fastest: K/V L2 reuse
    int nh = n*HEADS + h;
    size_t hoff = (size_t)nh * S_LEN * HD;
    int qrow0 = qt * 128;
    int wm0 = w * 16;
    int g = l >> 2, u = l & 3;

    // ---- stage Q tile into smem, load persistent A-frags
    #pragma unroll
    for (int i = 0; i < 2; i++){
        int idx = t + i*256;
        int row = idx >> 2, part = idx & 3;
        const char* qsrc = (const char*)(g_qhi + hoff + (size_t)(qrow0+row)*HD) + part*16;
        *(uint4*)(sm + SM_Q + row*RS + part*16) = *(const uint4*)qsrc;
    }

    // ---- prefetch tile 0
    {
        const char* ksrc = (const char*)(g_khi + hoff);
        const char* vhsrc = (const char*)(g_vhi + hoff);
        const char* vlsrc = (const char*)(g_vlo + hoff);
        #pragma unroll
        for (int i = 0; i < 2; i++){
            int idx = t + i*256;
            int row = idx >> 2, part = idx & 3;
            int go = row*64 + part*16, so = row*RS + part*16;
            cp_async16(smb + SM_K0  + so, ksrc + go);
            cp_async16(smb + SM_VH0 + so, vhsrc + go);
            cp_async16(smb + SM_VL0 + so, vlsrc + go);
        }
        if (t < 128)
            cp_async16(smb + SM_MB0 + t*16,
                       g_mbits + ((size_t)n*S_LEN + qrow0 + t)*32);
        CP_COMMIT();
    }
    __syncthreads();

    uint32_t qh0[4], qh1[4];
    {
        uint32_t rowb = (uint32_t)((wm0 + ((l & 8) ? 8 : 0) + (l & 7))*RS + ((l & 16) ? 16 : 0));
        ldsm_x4(qh0, smb + SM_Q + rowb);        // k 0-15
        ldsm_x4(qh1, smb + SM_Q + rowb + 32);   // k 16-31
    }

    float pv[4][4];
    #pragma unroll
    for (int i = 0; i < 4; i++){ pv[i][0]=0.f; pv[i][1]=0.f; pv[i][2]=0.f; pv[i][3]=0.f; }
    float l_r = 0.f, l_r8 = 0.f, inv_r = 0.f, inv_r8 = 0.f;

    float* wbase = attw + ((size_t)nh * S_LEN + qrow0) * S_LEN;

    for (int it = 0; it < 16; it++){
        int sweep = it >> 3, kt = it & 7, buf = it & 1;

        // ---- prefetch next tile into buf^1
        if (it < 15){
            int it2 = it + 1;
            int sw2 = it2 >> 3, kt2 = it2 & 7, b2 = it2 & 1;
            const char* ksrc = (const char*)(g_khi + hoff + (size_t)kt2*128*HD);
            const char* vhsrc = (const char*)(g_vhi + hoff + (size_t)kt2*128*HD);
            const char* vlsrc = (const char*)(g_vlo + hoff + (size_t)kt2*128*HD);
            #pragma unroll
            for (int i = 0; i < 2; i++){
                int idx = t + i*256;
                int row = idx >> 2, part = idx & 3;
                int go = row*64 + part*16, so = row*RS + part*16;
                cp_async16(smb + SM_K0 + b2*BUF + so, ksrc + go);
                if (sw2 == 0){
                    cp_async16(smb + SM_VH0 + b2*BUF + so, vhsrc + go);
                    cp_async16(smb + SM_VL0 + b2*BUF + so, vlsrc + go);
                }
            }
            if (t < 128)
                cp_async16(smb + SM_MB0 + b2*2048 + t*16,
                           g_mbits + ((size_t)n*S_LEN + qrow0 + t)*32 + kt2*4);
            CP_COMMIT();
            asm volatile("cp.async.wait_group 1;" ::: "memory");
        } else {
            asm volatile("cp.async.wait_group 0;" ::: "memory");
        }
        __syncthreads();

        uint32_t kbase  = smb + SM_K0  + buf*BUF;
        uint32_t vhbase = smb + SM_VH0 + buf*BUF;
        uint32_t vlbase = smb + SM_VL0 + buf*BUF;
        const uint32_t* mb = (const uint32_t*)(sm + SM_MB0 + buf*2048);

        // ---- hoist mask words for this thread's two rows (once per tile)
        uint32_t wr[4], wr8[4];
        #pragma unroll
        for (int j = 0; j < 4; j++){ wr[j] = mb[g*4 + j]; wr8[j] = mb[(g+8)*4 + j]; }

        if (sweep == 0){
            // ---- fused per-16-key chunk: QK -> mask/exp -> pack -> PV
            #pragma unroll
            for (int kc = 0; kc < 8; kc++){
                uint32_t bh0[4], bh1[4];
                uint32_t rbk = (uint32_t)((kc*16 + ((l & 16) ? 8 : 0) + (l & 7))*RS + ((l & 8) ? 16 : 0));
                ldsm_x4(bh0, kbase + rbk);
                ldsm_x4(bh1, kbase + rbk + 32);
                float qk0[4] = {0.f,0.f,0.f,0.f};
                float qk1[4] = {0.f,0.f,0.f,0.f};
                mma16816(qk0, qh0, bh0);   mma16816(qk1, qh0, bh0+2);
                mma16816(qk0, qh1, bh1);   mma16816(qk1, qh1, bh1+2);

                uint32_t w0 = wr[kc >> 1], w8 = wr8[kc >> 1];
                int sh0 = ((2*kc) & 3)*8 + u*2;
                int sh1 = ((2*kc+1) & 3)*8 + u*2;
                float e0 = ((w0 >> sh0)     & 1) ? ex2f(qk0[0]) : 0.f;
                float e1 = ((w0 >> (sh0+1)) & 1) ? ex2f(qk0[1]) : 0.f;
                float e2 = ((w8 >> sh0)     & 1) ? ex2f(qk0[2]) : 0.f;
                float e3 = ((w8 >> (sh0+1)) & 1) ? ex2f(qk0[3]) : 0.f;
                float e4 = ((w0 >> sh1)     & 1) ? ex2f(qk1[0]) : 0.f;
                float e5 = ((w0 >> (sh1+1)) & 1) ? ex2f(qk1[1]) : 0.f;
                float e6 = ((w8 >> sh1)     & 1) ? ex2f(qk1[2]) : 0.f;
                float e7 = ((w8 >> (sh1+1)) & 1) ? ex2f(qk1[3]) : 0.f;
                l_r  += e0 + e1 + e4 + e5;
                l_r8 += e2 + e3 + e6 + e7;

                uint32_t ah[4], al[4];
                ah[0] = packbf(e0, e1);
                ah[1] = packbf(e2, e3);
                ah[2] = packbf(e4, e5);
                ah[3] = packbf(e6, e7);
                al[0] = packbf(e0 - __uint_as_float(ah[0] << 16), e1 - __uint_as_float(ah[0] & 0xffff0000u));
                al[1] = packbf(e2 - __uint_as_float(ah[1] << 16), e3 - __uint_as_float(ah[1] & 0xffff0000u));
                al[2] = packbf(e4 - __uint_as_float(ah[2] << 16), e5 - __uint_as_float(ah[2] & 0xffff0000u));
                al[3] = packbf(e6 - __uint_as_float(ah[3] << 16), e7 - __uint_as_float(ah[3] & 0xffff0000u));

                uint32_t vh0[4], vh1[4], vl0[4], vl1[4];
                uint32_t rbv = (uint32_t)((kc*16 + ((l & 8) ? 8 : 0) + (l & 7))*RS + ((l & 16) ? 16 : 0));
                ldsm_x4t(vh0, vhbase + rbv);
                ldsm_x4t(vh1, vhbase + rbv + 32);
                ldsm_x4t(vl0, vlbase + rbv);
                ldsm_x4t(vl1, vlbase + rbv + 32);
                mma16816(pv[0], ah, vh0);   mma16816(pv[1], ah, vh0+2);
                mma16816(pv[2], ah, vh1);   mma16816(pv[3], ah, vh1+2);
                mma16816(pv[0], al, vh0);   mma16816(pv[1], al, vh0+2);
                mma16816(pv[2], al, vh1);   mma16816(pv[3], al, vh1+2);
                mma16816(pv[0], ah, vl0);   mma16816(pv[1], ah, vl0+2);
                mma16816(pv[2], ah, vl1);   mma16816(pv[3], ah, vl1+2);
            }
        } else {
            // ---- sweep 2: per-chunk QK -> exp -> normalized weights out
            #pragma unroll
            for (int np = 0; np < 8; np++){
                uint32_t bh0[4], bh1[4];
                uint32_t rbk = (uint32_t)((np*16 + ((l & 16) ? 8 : 0) + (l & 7))*RS + ((l & 8) ? 16 : 0));
                ldsm_x4(bh0, kbase + rbk);
                ldsm_x4(bh1, kbase + rbk + 32);
                float qk0[4] = {0.f,0.f,0.f,0.f};
                float qk1[4] = {0.f,0.f,0.f,0.f};
                mma16816(qk0, qh0, bh0);   mma16816(qk1, qh0, bh0+2);
                mma16816(qk0, qh1, bh1);   mma16816(qk1, qh1, bh1+2);

                uint32_t w0 = wr[np >> 1], w8 = wr8[np >> 1];
                int sh0 = ((2*np) & 3)*8 + u*2;
                int sh1 = ((2*np+1) & 3)*8 + u*2;
                float e0 = ((w0 >> sh0)     & 1) ? ex2f(qk0[0]) : 0.f;
                float e1 = ((w0 >> (sh0+1)) & 1) ? ex2f(qk0[1]) : 0.f;
                float e2 = ((w8 >> sh0)     & 1) ? ex2f(qk0[2]) : 0.f;
                float e3 = ((w8 >> (sh0+1)) & 1) ? ex2f(qk0[3]) : 0.f;
                float e4 = ((w0 >> sh1)     & 1) ? ex2f(qk1[0]) : 0.f;
                float e5 = ((w0 >> (sh1+1)) & 1) ? ex2f(qk1[1]) : 0.f;
                float e6 = ((w8 >> sh1)     & 1) ? ex2f(qk1[2]) : 0.f;
                float e7 = ((w8 >> (sh1+1)) & 1) ? ex2f(qk1[3]) : 0.f;

                float* wr0p = wbase + (size_t)(wm0 + g)*S_LEN     + kt*128 + np*16 + u*2;
                float* wr8p = wbase + (size_t)(wm0 + g + 8)*S_LEN + kt*128 + np*16 + u*2;
                float2 o;
                o.x = e0*inv_r;  o.y = e1*inv_r;  *(float2*)(wr0p) = o;
                o.x = e4*inv_r;  o.y = e5*inv_r;  *(float2*)(wr0p + 8) = o;
                o.x = e2*inv_r8; o.y = e3*inv_r8; *(float2*)(wr8p) = o;
                o.x = e6*inv_r8; o.y = e7*inv_r8; *(float2*)(wr8p + 8) = o;
            }
        }

        if (it == 7){
            // row-sum reduction + normalized ctx write (bf16 hi/lo packed)
            l_r  += __shfl_xor_sync(0xffffffffu, l_r, 1);
            l_r  += __shfl_xor_sync(0xffffffffu, l_r, 2);
            l_r8 += __shfl_xor_sync(0xffffffffu, l_r8, 1);
            l_r8 += __shfl_xor_sync(0xffffffffu, l_r8, 2);
            inv_r  = 1.0f / l_r;
            inv_r8 = 1.0f / l_r8;
            size_t r0 = (size_t)(n*S_LEN + qrow0 + wm0 + g);
            size_t r8 = r0 + 8;
            #pragma unroll
            for (int nt = 0; nt < 4; nt++){
                float x0 = pv[nt][0]*inv_r,  x1 = pv[nt][1]*inv_r;
                float x2 = pv[nt][2]*inv_r8, x3 = pv[nt][3]*inv_r8;
                uint32_t h0 = packbf(x0, x1);
                uint32_t h1 = packbf(x2, x3);
                uint32_t l0 = packbf(x0 - __uint_as_float(h0 << 16),
                                     x1 - __uint_as_float(h0 & 0xffff0000u));
                uint32_t l1 = packbf(x2 - __uint_as_float(h1 << 16),
                                     x3 - __uint_as_float(h1 & 0xffff0000u));
                int ci = h*16 + nt*4 + u;
                g_cxhi[r0*64 + ci] = h0;
                g_cxlo[r0*64 + ci] = l0;
                g_cxhi[r8*64 + ci] = h1;
                g_cxlo[r8*64 + ci] = l1;
            }
        }
        __syncthreads();
    }
}

// ============================================================
// Kernel 3: out = ctx @ Wo.T + bo via HMMA (ctx bf16 hi/lo, Wo hi/lo)
// ============================================================
#define ORS 272
__global__ __launch_bounds__(256) void out_kernel(
    const float* __restrict__ bo, float* __restrict__ out)
{
    extern __shared__ char sm[];
    uint32_t smb = smem_u32(sm);
    char* swhi = sm;
    char* swlo = sm + 128*ORS;
    float* sbo = (float*)(sm + 2*128*ORS);
    int t = threadIdx.x;
    int l = t & 31, w = t >> 5;
    int g = l >> 2, u = l & 3;

    #pragma unroll
    for (int i = 0; i < 8; i++){
        int idx = t + i*256;
        int row = idx >> 4, part = idx & 15;
        *(uint4*)(swhi + row*ORS + part*16) = ((const uint4*)g_wohi)[idx];
        *(uint4*)(swlo + row*ORS + part*16) = ((const uint4*)g_wolo)[idx];
    }
    if (t < 128) sbo[t] = __ldg(bo + t);
    __syncthreads();

    int R0 = blockIdx.x*128 + w*16;
    float c[16][4];
    #pragma unroll
    for (int i = 0; i < 16; i++){ c[i][0]=0.f; c[i][1]=0.f; c[i][2]=0.f; c[i][3]=0.f; }

    #pragma unroll
    for (int c8 = 0; c8 < 8; c8++){
        uint32_t ah[4], al[4];
        size_t rA = (size_t)(R0 + g)*64 + c8*8 + u;
        size_t rB = (size_t)(R0 + g + 8)*64 + c8*8 + u;
        ah[0] = __ldg(g_cxhi + rA);     ah[1] = __ldg(g_cxhi + rB);
        ah[2] = __ldg(g_cxhi + rA + 4); ah[3] = __ldg(g_cxhi + rB + 4);
        al[0] = __ldg(g_cxlo + rA);     al[1] = __ldg(g_cxlo + rB);
        al[2] = __ldg(g_cxlo + rA + 4); al[3] = __ldg(g_cxlo + rB + 4);
        #pragma unroll
        for (int np = 0; np < 8; np++){
            uint32_t bh[4], bl[4];
            uint32_t rb = (uint32_t)((np*16 + ((l & 16) ? 8 : 0) + (l & 7))*ORS + ((l & 8) ? 16 : 0) + c8*32);
            ldsm_x4(bh, smb + rb);
            ldsm_x4(bl, smb + 128*ORS + rb);
            mma16816(c[2*np],   ah, bh);     mma16816(c[2*np+1], ah, bh+2);
            mma16816(c[2*np],   al, bh);     mma16816(c[2*np+1], al, bh+2);
            mma16816(c[2*np],   ah, bl);     mma16816(c[2*np+1], ah, bl+2);
        }
    }

    float* o0 = out + (size_t)(R0 + g)*EMB + u*2;
    float* o8 = out + (size_t)(R0 + g + 8)*EMB + u*2;
    #pragma unroll
    for (int nt = 0; nt < 16; nt++){
        int col = nt*8 + u*2;
        float2 a; a.x = c[nt][0] + sbo[col]; a.y = c[nt][1] + sbo[col+1];
        float2 b; b.x = c[nt][2] + sbo[col]; b.y = c[nt][3] + sbo[col+1];
        *(float2*)(o0 + nt*8) = a;
        *(float2*)(o8 + nt*8) = b;
    }
}

// ============================================================
extern "C" void kernel_launch(void* const* d_in, const int* in_sizes, int n_in,
                              void* d_out, int out_size)
{
    const float* values = (const float*)d_in[0];
    const float* keys   = (const float*)d_in[1];
    const float* query  = (const float*)d_in[2];
    const int*   mask   = (const int*)d_in[3];
    const float* Wv     = (const float*)d_in[4];
    const float* Wk     = (const float*)d_in[5];
    const float* Wq     = (const float*)d_in[6];
    const float* Wo     = (const float*)d_in[7];
    const float* bo     = (const float*)d_in[8];

    float* out  = (float*)d_out;
    float* attw = out + (size_t)N_B*S_LEN*EMB;   // tuple order: (out, attention_weights)

    cudaFuncSetAttribute(attn_kernel, cudaFuncAttributeMaxDynamicSharedMemorySize, SM_TOTAL);
    cudaFuncSetAttribute(out_kernel,  cudaFuncAttributeMaxDynamicSharedMemorySize, 2*128*ORS + 512);

    maskbits_kernel<<<(N_B*S_LEN*(S_LEN/32))/256, 256>>>(mask);
    woprep_kernel<<<EMB*EMB/256, 256>>>(Wo);
    proj_kernel<<<(N_B*S_LEN)/16, 256>>>(values, keys, query, Wv, Wk, Wq);
    attn_kernel<<<N_B*HEADS*(S_LEN/128), 256, SM_TOTAL>>>(attw);
    out_kernel<<<(N_B*S_LEN)/128, 256, 2*128*ORS + 512>>>(bo, out);
}

// round 16
// speedup vs baseline: 1.1109x; 1.0640x over previous
#include <cuda_runtime.h>
#include <cuda_bf16.h>
#include <cstdint>

#define N_B 32
#define S_LEN 1024
#define HEADS 4
#define HD 32
#define EMB 128
#define LOG2E 1.4426950408889634f
#define SCALE 0.08838834764831845f      // 1/sqrt(128)
#define QSCALE (SCALE * LOG2E)

// ---------------- device scratch ----------------
__device__ __nv_bfloat16 g_qhi[N_B*HEADS*S_LEN*HD];
__device__ __nv_bfloat16 g_khi[N_B*HEADS*S_LEN*HD];
__device__ __nv_bfloat16 g_vhi[N_B*HEADS*S_LEN*HD];
__device__ __nv_bfloat16 g_vlo[N_B*HEADS*S_LEN*HD];
__device__ uint32_t g_mbits[(size_t)N_B*S_LEN*(S_LEN/32)];
__device__ uint32_t g_cxhi[(size_t)N_B*S_LEN*64];    // ctx bf16x2 (even,odd cols)
__device__ uint32_t g_cxlo[(size_t)N_B*S_LEN*64];
__device__ __nv_bfloat16 g_wohi[EMB*EMB];
__device__ __nv_bfloat16 g_wolo[EMB*EMB];

// ---------------- helpers ----------------
__device__ __forceinline__ uint32_t smem_u32(const void* p){
    uint32_t a;
    asm("{ .reg .u64 t; cvta.to.shared.u64 t, %1; cvt.u32.u64 %0, t; }" : "=r"(a) : "l"(p));
    return a;
}
__device__ __forceinline__ float ex2f(float x){
    float y; asm("ex2.approx.f32 %0, %1;" : "=f"(y) : "f"(x)); return y;
}
__device__ __forceinline__ uint32_t packbf(float lo, float hi){
    uint32_t d; asm("cvt.rn.bf16x2.f32 %0, %1, %2;" : "=r"(d) : "f"(hi), "f"(lo)); return d;
}
__device__ __forceinline__ void ldsm_x4(uint32_t* r, uint32_t addr){
    asm volatile("ldmatrix.sync.aligned.m8n8.x4.shared.b16 {%0,%1,%2,%3}, [%4];"
        : "=r"(r[0]), "=r"(r[1]), "=r"(r[2]), "=r"(r[3]) : "r"(addr));
}
__device__ __forceinline__ void ldsm_x4t(uint32_t* r, uint32_t addr){
    asm volatile("ldmatrix.sync.aligned.m8n8.x4.trans.shared.b16 {%0,%1,%2,%3}, [%4];"
        : "=r"(r[0]), "=r"(r[1]), "=r"(r[2]), "=r"(r[3]) : "r"(addr));
}
__device__ __forceinline__ void mma16816(float* c, const uint32_t* a, const uint32_t* b){
    asm volatile("mma.sync.aligned.m16n8k16.row.col.f32.bf16.bf16.f32 "
        "{%0,%1,%2,%3}, {%4,%5,%6,%7}, {%8,%9}, {%0,%1,%2,%3};"
        : "+f"(c[0]), "+f"(c[1]), "+f"(c[2]), "+f"(c[3])
        : "r"(a[0]), "r"(a[1]), "r"(a[2]), "r"(a[3]), "r"(b[0]), "r"(b[1]));
}
__device__ __forceinline__ void cp_async16(uint32_t dst, const void* src){
    asm volatile("cp.async.cg.shared.global [%0], [%1], 16;" :: "r"(dst), "l"(src));
}
#define CP_COMMIT() asm volatile("cp.async.commit_group;" ::: "memory")

// ---------------- attn smem layout (byte offsets; row stride 80B) ----------------
#define RS 80
#define BUF 10240
#define SM_K0  0
#define SM_VH0 20480
#define SM_VL0 40960
#define SM_Q   61440
#define SM_MB0 71680
#define SM_TOTAL 76800

// ============================================================
// Kernel 0a: bit-pack the mask
// ============================================================
__global__ __launch_bounds__(256) void maskbits_kernel(const int* __restrict__ mask)
{
    size_t w = (size_t)blockIdx.x * 256 + threadIdx.x;
    const int4* p = (const int4*)(mask + w * 32);
    uint32_t b = 0;
    #pragma unroll
    for (int i = 0; i < 8; i++){
        int4 v = __ldg(p + i);
        b |= (v.x != 0 ? 1u : 0u) << (i*4 + 0);
        b |= (v.y != 0 ? 1u : 0u) << (i*4 + 1);
        b |= (v.z != 0 ? 1u : 0u) << (i*4 + 2);
        b |= (v.w != 0 ? 1u : 0u) << (i*4 + 3);
    }
    g_mbits[w] = b;
}

// ============================================================
// Kernel 0b: split Wo into bf16 hi/lo
// ============================================================
__global__ __launch_bounds__(256) void woprep_kernel(const float* __restrict__ Wo)
{
    int i = blockIdx.x * 256 + threadIdx.x;      // 16384
    float w = __ldg(Wo + i);
    __nv_bfloat16 hi = __float2bfloat16(w);
    g_wohi[i] = hi;
    g_wolo[i] = __float2bfloat16(w - __bfloat162float(hi));
}

// ============================================================
// Kernel 1: projections -> bf16 (Q pre-scaled); vectorized smem reads
// ============================================================
__global__ __launch_bounds__(256) void proj_kernel(
    const float* __restrict__ vin, const float* __restrict__ kin,
    const float* __restrict__ qin,
    const float* __restrict__ Wv, const float* __restrict__ Wk,
    const float* __restrict__ Wq)
{
    __shared__ float sW[3][32*36];      // pad 36: float4-aligned rows, conflict-free
    __shared__ float srow[3][16*128];
    int t = threadIdx.x;
    for (int i = t; i < 1024; i += 256){
        int d = i >> 5, e = i & 31;
        sW[0][d*36+e] = __ldg(Wv + i);
        sW[1][d*36+e] = __ldg(Wk + i);
        sW[2][d*36+e] = __ldg(Wq + i);
    }
    int row0 = blockIdx.x * 16;
    const float4* s0 = (const float4*)(vin + (size_t)row0*128);
    const float4* s1 = (const float4*)(kin + (size_t)row0*128);
    const float4* s2 = (const float4*)(qin + (size_t)row0*128);
    #pragma unroll
    for (int i = 0; i < 2; i++){
        int idx = t + i*256;
        ((float4*)srow[0])[idx] = __ldg(s0 + idx);
        ((float4*)srow[1])[idx] = __ldg(s1 + idx);
        ((float4*)srow[2])[idx] = __ldg(s2 + idx);
    }
    __syncthreads();
    int half = t >> 7;
    int tt = t & 127;
    int h = tt >> 5, d = tt & 31;
    int n = row0 >> 10;
    int sbase = (row0 & 1023) + half*8;
    const float4* wv4 = (const float4*)&sW[0][d*36];
    const float4* wk4 = (const float4*)&sW[1][d*36];
    const float4* wq4 = (const float4*)&sW[2][d*36];
    for (int i = 0; i < 8; i++){
        int ri = half*8 + i;
        float av = 0.f, ak = 0.f, aq = 0.f;
        const float4* rv = (const float4*)&srow[0][ri*128 + h*32];
        const float4* rk = (const float4*)&srow[1][ri*128 + h*32];
        const float4* rq = (const float4*)&srow[2][ri*128 + h*32];
        #pragma unroll
        for (int e4 = 0; e4 < 8; e4++){
            float4 w0 = wv4[e4], x0 = rv[e4];
            av = fmaf(w0.x, x0.x, av); av = fmaf(w0.y, x0.y, av);
            av = fmaf(w0.z, x0.z, av); av = fmaf(w0.w, x0.w, av);
            float4 w1 = wk4[e4], x1 = rk[e4];
            ak = fmaf(w1.x, x1.x, ak); ak = fmaf(w1.y, x1.y, ak);
            ak = fmaf(w1.z, x1.z, ak); ak = fmaf(w1.w, x1.w, ak);
            float4 w2 = wq4[e4], x2 = rq[e4];
            aq = fmaf(w2.x, x2.x, aq); aq = fmaf(w2.y, x2.y, aq);
            aq = fmaf(w2.z, x2.z, aq); aq = fmaf(w2.w, x2.w, aq);
        }
        __nv_bfloat16 vh = __float2bfloat16(av);
        size_t o = ((size_t)(n*HEADS + h)*S_LEN + sbase + i)*HD + d;
        g_qhi[o] = __float2bfloat16(aq * QSCALE);
        g_khi[o] = __float2bfloat16(ak);
        g_vhi[o] = vh;
        g_vlo[o] = __float2bfloat16(av - __bfloat162float(vh));
    }
}

// ============================================================
// Kernel 2: fused HMMA attention, cp.async double-buffered,
// per-chunk QK->exp->PV fusion; warp-uniform mask fast-path.
// ============================================================
__global__ __launch_bounds__(256) void attn_kernel(float* __restrict__ attw)
{
    extern __shared__ char sm[];
    uint32_t smb = smem_u32(sm);
    int t = threadIdx.x;
    int l = t & 31, w = t >> 5;
    int bid = blockIdx.x;
    int qt = bid & 7, h = (bid >> 3) & 3, n = bid >> 5;   // qt fastest: K/V L2 reuse
    int nh = n*HEADS + h;
    size_t hoff = (size_t)nh * S_LEN * HD;
    int qrow0 = qt * 128;
    int wm0 = w * 16;
    int g = l >> 2, u = l & 3;

    // ---- stage Q tile into smem, load persistent A-frags
    #pragma unroll
    for (int i = 0; i < 2; i++){
        int idx = t + i*256;
        int row = idx >> 2, part = idx & 3;
        const char* qsrc = (const char*)(g_qhi + hoff + (size_t)(qrow0+row)*HD) + part*16;
        *(uint4*)(sm + SM_Q + row*RS + part*16) = *(const uint4*)qsrc;
    }

    // ---- prefetch tile 0
    {
        const char* ksrc = (const char*)(g_khi + hoff);
        const char* vhsrc = (const char*)(g_vhi + hoff);
        const char* vlsrc = (const char*)(g_vlo + hoff);
        #pragma unroll
        for (int i = 0; i < 2; i++){
            int idx = t + i*256;
            int row = idx >> 2, part = idx & 3;
            int go = row*64 + part*16, so = row*RS + part*16;
            cp_async16(smb + SM_K0  + so, ksrc + go);
            cp_async16(smb + SM_VH0 + so, vhsrc + go);
            cp_async16(smb + SM_VL0 + so, vlsrc + go);
        }
        if (t < 128)
            cp_async16(smb + SM_MB0 + t*16,
                       g_mbits + ((size_t)n*S_LEN + qrow0 + t)*32);
        CP_COMMIT();
    }
    __syncthreads();

    uint32_t qh0[4], qh1[4];
    {
        uint32_t rowb = (uint32_t)((wm0 + ((l & 8) ? 8 : 0) + (l & 7))*RS + ((l & 16) ? 16 : 0));
        ldsm_x4(qh0, smb + SM_Q + rowb);        // k 0-15
        ldsm_x4(qh1, smb + SM_Q + rowb + 32);   // k 16-31
    }

    float pv[4][4];
    #pragma unroll
    for (int i = 0; i < 4; i++){ pv[i][0]=0.f; pv[i][1]=0.f; pv[i][2]=0.f; pv[i][3]=0.f; }
    float l_r = 0.f, l_r8 = 0.f, inv_r = 0.f, inv_r8 = 0.f;

    float* wbase = attw + ((size_t)nh * S_LEN + qrow0) * S_LEN;

    for (int it = 0; it < 16; it++){
        int sweep = it >> 3, kt = it & 7, buf = it & 1;

        // ---- prefetch next tile into buf^1
        if (it < 15){
            int it2 = it + 1;
            int sw2 = it2 >> 3, kt2 = it2 & 7, b2 = it2 & 1;
            const char* ksrc = (const char*)(g_khi + hoff + (size_t)kt2*128*HD);
            const char* vhsrc = (const char*)(g_vhi + hoff + (size_t)kt2*128*HD);
            const char* vlsrc = (const char*)(g_vlo + hoff + (size_t)kt2*128*HD);
            #pragma unroll
            for (int i = 0; i < 2; i++){
                int idx = t + i*256;
                int row = idx >> 2, part = idx & 3;
                int go = row*64 + part*16, so = row*RS + part*16;
                cp_async16(smb + SM_K0 + b2*BUF + so, ksrc + go);
                if (sw2 == 0){
                    cp_async16(smb + SM_VH0 + b2*BUF + so, vhsrc + go);
                    cp_async16(smb + SM_VL0 + b2*BUF + so, vlsrc + go);
                }
            }
            if (t < 128)
                cp_async16(smb + SM_MB0 + b2*2048 + t*16,
                           g_mbits + ((size_t)n*S_LEN + qrow0 + t)*32 + kt2*4);
            CP_COMMIT();
            asm volatile("cp.async.wait_group 1;" ::: "memory");
        } else {
            asm volatile("cp.async.wait_group 0;" ::: "memory");
        }
        __syncthreads();

        uint32_t kbase  = smb + SM_K0  + buf*BUF;
        uint32_t vhbase = smb + SM_VH0 + buf*BUF;
        uint32_t vlbase = smb + SM_VL0 + buf*BUF;
        const uint32_t* mb = (const uint32_t*)(sm + SM_MB0 + buf*2048);

        // ---- hoist mask words; warp-uniform all-ones fast-path flag
        uint32_t wr[4], wr8[4];
        #pragma unroll
        for (int j = 0; j < 4; j++){ wr[j] = mb[g*4 + j]; wr8[j] = mb[(g+8)*4 + j]; }
        uint32_t am = wr[0] & wr[1] & wr[2] & wr[3] & wr8[0] & wr8[1] & wr8[2] & wr8[3];
        int fastm = __all_sync(0xffffffffu, am == 0xffffffffu);

        if (sweep == 0){
            // ---- fused per-16-key chunk: QK -> mask/exp -> pack -> PV
            #pragma unroll
            for (int kc = 0; kc < 8; kc++){
                uint32_t bh0[4], bh1[4];
                uint32_t rbk = (uint32_t)((kc*16 + ((l & 16) ? 8 : 0) + (l & 7))*RS + ((l & 8) ? 16 : 0));
                ldsm_x4(bh0, kbase + rbk);
                ldsm_x4(bh1, kbase + rbk + 32);
                float qk0[4] = {0.f,0.f,0.f,0.f};
                float qk1[4] = {0.f,0.f,0.f,0.f};
                mma16816(qk0, qh0, bh0);   mma16816(qk1, qh0, bh0+2);
                mma16816(qk0, qh1, bh1);   mma16816(qk1, qh1, bh1+2);

                float e0 = ex2f(qk0[0]);
                float e1 = ex2f(qk0[1]);
                float e2 = ex2f(qk0[2]);
                float e3 = ex2f(qk0[3]);
                float e4 = ex2f(qk1[0]);
                float e5 = ex2f(qk1[1]);
                float e6 = ex2f(qk1[2]);
                float e7 = ex2f(qk1[3]);
                if (!fastm){
                    uint32_t w0 = wr[kc >> 1], w8 = wr8[kc >> 1];
                    int sh0 = ((2*kc) & 3)*8 + u*2;
                    int sh1 = ((2*kc+1) & 3)*8 + u*2;
                    e0 = ((w0 >> sh0)     & 1) ? e0 : 0.f;
                    e1 = ((w0 >> (sh0+1)) & 1) ? e1 : 0.f;
                    e2 = ((w8 >> sh0)     & 1) ? e2 : 0.f;
                    e3 = ((w8 >> (sh0+1)) & 1) ? e3 : 0.f;
                    e4 = ((w0 >> sh1)     & 1) ? e4 : 0.f;
                    e5 = ((w0 >> (sh1+1)) & 1) ? e5 : 0.f;
                    e6 = ((w8 >> sh1)     & 1) ? e6 : 0.f;
                    e7 = ((w8 >> (sh1+1)) & 1) ? e7 : 0.f;
                }
                l_r  += e0 + e1 + e4 + e5;
                l_r8 += e2 + e3 + e6 + e7;

                uint32_t ah[4], al[4];
                ah[0] = packbf(e0, e1);
                ah[1] = packbf(e2, e3);
                ah[2] = packbf(e4, e5);
                ah[3] = packbf(e6, e7);
                al[0] = packbf(e0 - __uint_as_float(ah[0] << 16), e1 - __uint_as_float(ah[0] & 0xffff0000u));
                al[1] = packbf(e2 - __uint_as_float(ah[1] << 16), e3 - __uint_as_float(ah[1] & 0xffff0000u));
                al[2] = packbf(e4 - __uint_as_float(ah[2] << 16), e5 - __uint_as_float(ah[2] & 0xffff0000u));
                al[3] = packbf(e6 - __uint_as_float(ah[3] << 16), e7 - __uint_as_float(ah[3] & 0xffff0000u));

                uint32_t vh0[4], vh1[4], vl0[4], vl1[4];
                uint32_t rbv = (uint32_t)((kc*16 + ((l & 8) ? 8 : 0) + (l & 7))*RS + ((l & 16) ? 16 : 0));
                ldsm_x4t(vh0, vhbase + rbv);
                ldsm_x4t(vh1, vhbase + rbv + 32);
                ldsm_x4t(vl0, vlbase + rbv);
                ldsm_x4t(vl1, vlbase + rbv + 32);
                mma16816(pv[0], ah, vh0);   mma16816(pv[1], ah, vh0+2);
                mma16816(pv[2], ah, vh1);   mma16816(pv[3], ah, vh1+2);
                mma16816(pv[0], al, vh0);   mma16816(pv[1], al, vh0+2);
                mma16816(pv[2], al, vh1);   mma16816(pv[3], al, vh1+2);
                mma16816(pv[0], ah, vl0);   mma16816(pv[1], ah, vl0+2);
                mma16816(pv[2], ah, vl1);   mma16816(pv[3], ah, vl1+2);
            }
        } else {
            // ---- sweep 2: per-chunk QK -> exp -> normalized weights out
            #pragma unroll
            for (int np = 0; np < 8; np++){
                uint32_t bh0[4], bh1[4];
                uint32_t rbk = (uint32_t)((np*16 + ((l & 16) ? 8 : 0) + (l & 7))*RS + ((l & 8) ? 16 : 0));
                ldsm_x4(bh0, kbase + rbk);
                ldsm_x4(bh1, kbase + rbk + 32);
                float qk0[4] = {0.f,0.f,0.f,0.f};
                float qk1[4] = {0.f,0.f,0.f,0.f};
                mma16816(qk0, qh0, bh0);   mma16816(qk1, qh0, bh0+2);
                mma16816(qk0, qh1, bh1);   mma16816(qk1, qh1, bh1+2);

                float e0 = ex2f(qk0[0]);
                float e1 = ex2f(qk0[1]);
                float e2 = ex2f(qk0[2]);
                float e3 = ex2f(qk0[3]);
                float e4 = ex2f(qk1[0]);
                float e5 = ex2f(qk1[1]);
                float e6 = ex2f(qk1[2]);
                float e7 = ex2f(qk1[3]);
                if (!fastm){
                    uint32_t w0 = wr[np >> 1], w8 = wr8[np >> 1];
                    int sh0 = ((2*np) & 3)*8 + u*2;
                    int sh1 = ((2*np+1) & 3)*8 + u*2;
                    e0 = ((w0 >> sh0)     & 1) ? e0 : 0.f;
                    e1 = ((w0 >> (sh0+1)) & 1) ? e1 : 0.f;
                    e2 = ((w8 >> sh0)     & 1) ? e2 : 0.f;
                    e3 = ((w8 >> (sh0+1)) & 1) ? e3 : 0.f;
                    e4 = ((w0 >> sh1)     & 1) ? e4 : 0.f;
                    e5 = ((w0 >> (sh1+1)) & 1) ? e5 : 0.f;
                    e6 = ((w8 >> sh1)     & 1) ? e6 : 0.f;
                    e7 = ((w8 >> (sh1+1)) & 1) ? e7 : 0.f;
                }

                float* wr0p = wbase + (size_t)(wm0 + g)*S_LEN     + kt*128 + np*16 + u*2;
                float* wr8p = wbase + (size_t)(wm0 + g + 8)*S_LEN + kt*128 + np*16 + u*2;
                float2 o;
                o.x = e0*inv_r;  o.y = e1*inv_r;  *(float2*)(wr0p) = o;
                o.x = e4*inv_r;  o.y = e5*inv_r;  *(float2*)(wr0p + 8) = o;
                o.x = e2*inv_r8; o.y = e3*inv_r8; *(float2*)(wr8p) = o;
                o.x = e6*inv_r8; o.y = e7*inv_r8; *(float2*)(wr8p + 8) = o;
            }
        }

        if (it == 7){
            // row-sum reduction + normalized ctx write (bf16 hi/lo packed)
            l_r  += __shfl_xor_sync(0xffffffffu, l_r, 1);
            l_r  += __shfl_xor_sync(0xffffffffu, l_r, 2);
            l_r8 += __shfl_xor_sync(0xffffffffu, l_r8, 1);
            l_r8 += __shfl_xor_sync(0xffffffffu, l_r8, 2);
            inv_r  = 1.0f / l_r;
            inv_r8 = 1.0f / l_r8;
            size_t r0 = (size_t)(n*S_LEN + qrow0 + wm0 + g);
            size_t r8 = r0 + 8;
            #pragma unroll
            for (int nt = 0; nt < 4; nt++){
                float x0 = pv[nt][0]*inv_r,  x1 = pv[nt][1]*inv_r;
                float x2 = pv[nt][2]*inv_r8, x3 = pv[nt][3]*inv_r8;
                uint32_t h0 = packbf(x0, x1);
                uint32_t h1 = packbf(x2, x3);
                uint32_t l0 = packbf(x0 - __uint_as_float(h0 << 16),
                                     x1 - __uint_as_float(h0 & 0xffff0000u));
                uint32_t l1 = packbf(x2 - __uint_as_float(h1 << 16),
                                     x3 - __uint_as_float(h1 & 0xffff0000u));
                int ci = h*16 + nt*4 + u;
                g_cxhi[r0*64 + ci] = h0;
                g_cxlo[r0*64 + ci] = l0;
                g_cxhi[r8*64 + ci] = h1;
                g_cxlo[r8*64 + ci] = l1;
            }
        }
        __syncthreads();
    }
}

// ============================================================
// Kernel 3: out = ctx @ Wo.T + bo via HMMA (ctx bf16 hi/lo, Wo hi/lo)
// ============================================================
#define ORS 272
__global__ __launch_bounds__(256) void out_kernel(
    const float* __restrict__ bo, float* __restrict__ out)
{
    extern __shared__ char sm[];
    uint32_t smb = smem_u32(sm);
    char* swhi = sm;
    char* swlo = sm + 128*ORS;
    float* sbo = (float*)(sm + 2*128*ORS);
    int t = threadIdx.x;
    int l = t & 31, w = t >> 5;
    int g = l >> 2, u = l & 3;

    #pragma unroll
    for (int i = 0; i < 8; i++){
        int idx = t + i*256;
        int row = idx >> 4, part = idx & 15;
        *(uint4*)(swhi + row*ORS + part*16) = ((const uint4*)g_wohi)[idx];
        *(uint4*)(swlo + row*ORS + part*16) = ((const uint4*)g_wolo)[idx];
    }
    if (t < 128) sbo[t] = __ldg(bo + t);
    __syncthreads();

    int R0 = blockIdx.x*128 + w*16;
    float c[16][4];
    #pragma unroll
    for (int i = 0; i < 16; i++){ c[i][0]=0.f; c[i][1]=0.f; c[i][2]=0.f; c[i][3]=0.f; }

    #pragma unroll
    for (int c8 = 0; c8 < 8; c8++){
        uint32_t ah[4], al[4];
        size_t rA = (size_t)(R0 + g)*64 + c8*8 + u;
        size_t rB = (size_t)(R0 + g + 8)*64 + c8*8 + u;
        ah[0] = __ldg(g_cxhi + rA);     ah[1] = __ldg(g_cxhi + rB);
        ah[2] = __ldg(g_cxhi + rA + 4); ah[3] = __ldg(g_cxhi + rB + 4);
        al[0] = __ldg(g_cxlo + rA);     al[1] = __ldg(g_cxlo + rB);
        al[2] = __ldg(g_cxlo + rA + 4); al[3] = __ldg(g_cxlo + rB + 4);
        #pragma unroll
        for (int np = 0; np < 8; np++){
            uint32_t bh[4], bl[4];
            uint32_t rb = (uint32_t)((np*16 + ((l & 16) ? 8 : 0) + (l & 7))*ORS + ((l & 8) ? 16 : 0) + c8*32);
            ldsm_x4(bh, smb + rb);
            ldsm_x4(bl, smb + 128*ORS + rb);
            mma16816(c[2*np],   ah, bh);     mma16816(c[2*np+1], ah, bh+2);
            mma16816(c[2*np],   al, bh);     mma16816(c[2*np+1], al, bh+2);
            mma16816(c[2*np],   ah, bl);     mma16816(c[2*np+1], ah, bl+2);
        }
    }

    float* o0 = out + (size_t)(R0 + g)*EMB + u*2;
    float* o8 = out + (size_t)(R0 + g + 8)*EMB + u*2;
    #pragma unroll
    for (int nt = 0; nt < 16; nt++){
        int col = nt*8 + u*2;
        float2 a; a.x = c[nt][0] + sbo[col]; a.y = c[nt][1] + sbo[col+1];
        float2 b; b.x = c[nt][2] + sbo[col]; b.y = c[nt][3] + sbo[col+1];
        *(float2*)(o0 + nt*8) = a;
        *(float2*)(o8 + nt*8) = b;
    }
}

// ============================================================
extern "C" void kernel_launch(void* const* d_in, const int* in_sizes, int n_in,
                              void* d_out, int out_size)
{
    const float* values = (const float*)d_in[0];
    const float* keys   = (const float*)d_in[1];
    const float* query  = (const float*)d_in[2];
    const int*   mask   = (const int*)d_in[3];
    const float* Wv     = (const float*)d_in[4];
    const float* Wk     = (const float*)d_in[5];
    const float* Wq     = (const float*)d_in[6];
    const float* Wo     = (const float*)d_in[7];
    const float* bo     = (const float*)d_in[8];

    float* out  = (float*)d_out;
    float* attw = out + (size_t)N_B*S_LEN*EMB;   // tuple order: (out, attention_weights)

    cudaFuncSetAttribute(attn_kernel, cudaFuncAttributeMaxDynamicSharedMemorySize, SM_TOTAL);
    cudaFuncSetAttribute(out_kernel,  cudaFuncAttributeMaxDynamicSharedMemorySize, 2*128*ORS + 512);

    maskbits_kernel<<<(N_B*S_LEN*(S_LEN/32))/256, 256>>>(mask);
    woprep_kernel<<<EMB*EMB/256, 256>>>(Wo);
    proj_kernel<<<(N_B*S_LEN)/16, 256>>>(values, keys, query, Wv, Wk, Wq);
    attn_kernel<<<N_B*HEADS*(S_LEN/128), 256, SM_TOTAL>>>(attw);
    out_kernel<<<(N_B*S_LEN)/128, 256, 2*128*ORS + 512>>>(bo, out);
}